// round 2
// baseline (speedup 1.0000x reference)
#include <cuda_runtime.h>
#include <math.h>
#include <stdint.h>

#define B_SZ 4
#define SEQ 2048
#define DM 1024
#define ST 16
#define MROWS (B_SZ * SEQ)   // 8192

// ---------------- scratch (__device__ globals; no allocation allowed) ----------------
__device__ float  g_delta[MROWS * DM];      // softplus(x@Wd+bd), 32 MB
__device__ float2 g_BC[MROWS * ST];         // (B, C) interleaved per (row, n), 1 MB
__device__ float  g_WT[32 * DM];            // rows 0-15: Wb^T, rows 16-31: Wc^T

// ---------------- prep: transpose Wb, Wc into g_WT ----------------
__global__ void prep_wt_kernel(const float* __restrict__ Wb, const float* __restrict__ Wc) {
    int i = blockIdx.x * blockDim.x + threadIdx.x;   // 0 .. 32767
    if (i < ST * DM) {
        int col = i & 15, k = i >> 4;
        g_WT[col * DM + k] = Wb[i];
    } else {
        int j = i - ST * DM;
        int col = j & 15, k = j >> 4;
        g_WT[(16 + col) * DM + k] = Wc[j];
    }
}

// ================== TF32 tensor-core GEMM: delta = softplus(X @ Wd + bd) ==================
// X: [8192,1024] row-major, Wd: [1024,1024] row-major (K x N), out g_delta [8192,1024].
// 3xTF32 split for ~fp32 accuracy: D = Ah*Bh + Al*Bh + Ah*Bl.
// Block tile 128x128, BK=16 (2 k8-steps per stage), 8 warps (2 M x 4 N), warp tile 64x32.
// Smem holds fragments pre-permuted into mma register order.

__device__ __forceinline__ void split_tf32(float v, float& hi, float& lo) {
    uint32_t h;
    asm("cvt.rna.tf32.f32 %0, %1;" : "=r"(h) : "f"(v));
    float hf = __uint_as_float(h);
    float l = v - hf;
    uint32_t lt;
    asm("cvt.rna.tf32.f32 %0, %1;" : "=r"(lt) : "f"(l));
    hi = hf; lo = __uint_as_float(lt);
}

__device__ __forceinline__ void mma_tf32(float* c, const uint4& a, const uint2& b) {
    asm volatile(
        "mma.sync.aligned.m16n8k8.row.col.f32.tf32.tf32.f32 "
        "{%0,%1,%2,%3},{%4,%5,%6,%7},{%8,%9},{%0,%1,%2,%3};\n"
        : "+f"(c[0]), "+f"(c[1]), "+f"(c[2]), "+f"(c[3])
        : "r"(a.x), "r"(a.y), "r"(a.z), "r"(a.w), "r"(b.x), "r"(b.y));
}

__device__ __forceinline__ float softplus_f(float z) {
    return fmaxf(z, 0.f) + log1pf(__expf(-fabsf(z)));
}

#define GBM 128
#define GBN 128
#define GBK 16   // 2 k8-steps per stage
#define NSTAGE (DM / GBK)   // 64

__global__ __launch_bounds__(256, 1)
void gemm_tf32_softplus_kernel(const float* __restrict__ X, const float* __restrict__ W,
                               const float* __restrict__ bias) {
    // fragment-order smem: Asm[ks][mtile 0..7][hi/lo][lane*4 + r]
    __shared__ float Asm[2][8][2][128];   // 16 KB
    __shared__ float Bsm[2][16][2][64];   // 16 KB

    const int tid  = threadIdx.x;
    const int lane = tid & 31;
    const int wid  = tid >> 5;        // 0..7
    const int wm   = wid & 1;         // warp M (64 rows)
    const int wn   = wid >> 1;        // warp N (32 cols)
    const int bm   = blockIdx.y * GBM;
    const int bn   = blockIdx.x * GBN;

    // A loader: (row = tid>>1, kk base = (tid&1)*4), plus +8 in k
    const int arow = tid >> 1;
    const int akk  = (tid & 1) * 4;
    // B loader: (kk = tid>>5, col base = (tid&31)*4), plus +8 in k
    const int bkk  = tid >> 5;
    const int bcolb = (tid & 31) * 4;

    float acc[4][4][4];
#pragma unroll
    for (int i = 0; i < 4; ++i)
#pragma unroll
        for (int j = 0; j < 4; ++j)
#pragma unroll
            for (int r = 0; r < 4; ++r) acc[i][j][r] = 0.f;

    const float* Arow = X + (size_t)(bm + arow) * DM;

    // prologue: load stage 0
    float4 va0 = *(const float4*)&Arow[akk];
    float4 va1 = *(const float4*)&Arow[akk + 8];
    float4 vb0 = *(const float4*)&W[(size_t)bkk * DM + bn + bcolb];
    float4 vb1 = *(const float4*)&W[(size_t)(bkk + 8) * DM + bn + bcolb];

    for (int s = 0; s < NSTAGE; ++s) {
        // ---- STS with hi/lo split ----
        {
            // A part: float4 (arow, kkb) -> Asm[ks][mt][hl][g*16 + e*4 + r]
            const int mt = arow >> 4, ml = arow & 15, g = ml & 7, rb0 = ml >> 3;
            {
                const int ks = akk >> 3, rb1 = (akk >> 2) & 1, r = rb0 + 2 * rb1;
                float* hb = &Asm[ks][mt][0][g * 16 + r];
                float* lb = &Asm[ks][mt][1][g * 16 + r];
                float h, l;
                split_tf32(va0.x, h, l); hb[0]  = h; lb[0]  = l;
                split_tf32(va0.y, h, l); hb[4]  = h; lb[4]  = l;
                split_tf32(va0.z, h, l); hb[8]  = h; lb[8]  = l;
                split_tf32(va0.w, h, l); hb[12] = h; lb[12] = l;
            }
            {
                const int kkb = akk + 8;
                const int ks = kkb >> 3, rb1 = (kkb >> 2) & 1, r = rb0 + 2 * rb1;
                float* hb = &Asm[ks][mt][0][g * 16 + r];
                float* lb = &Asm[ks][mt][1][g * 16 + r];
                float h, l;
                split_tf32(va1.x, h, l); hb[0]  = h; lb[0]  = l;
                split_tf32(va1.y, h, l); hb[4]  = h; lb[4]  = l;
                split_tf32(va1.z, h, l); hb[8]  = h; lb[8]  = l;
                split_tf32(va1.w, h, l); hb[12] = h; lb[12] = l;
            }
            // B part: float4 (kk, colb) -> Bsm[ks][nt][hl][nl*8 + t*2 + rb]
            const int nt = bcolb >> 3, nl0 = bcolb & 7;
            {
                const int ks = bkk >> 3, kl = bkk & 7, t = kl & 3, rb = kl >> 2;
                float* hb = &Bsm[ks][nt][0][nl0 * 8 + t * 2 + rb];
                float* lb = &Bsm[ks][nt][1][nl0 * 8 + t * 2 + rb];
                float h, l;
                split_tf32(vb0.x, h, l); hb[0]  = h; lb[0]  = l;
                split_tf32(vb0.y, h, l); hb[8]  = h; lb[8]  = l;
                split_tf32(vb0.z, h, l); hb[16] = h; lb[16] = l;
                split_tf32(vb0.w, h, l); hb[24] = h; lb[24] = l;
            }
            {
                const int kk = bkk + 8;
                const int ks = kk >> 3, kl = kk & 7, t = kl & 3, rb = kl >> 2;
                float* hb = &Bsm[ks][nt][0][nl0 * 8 + t * 2 + rb];
                float* lb = &Bsm[ks][nt][1][nl0 * 8 + t * 2 + rb];
                float h, l;
                split_tf32(vb1.x, h, l); hb[0]  = h; lb[0]  = l;
                split_tf32(vb1.y, h, l); hb[8]  = h; lb[8]  = l;
                split_tf32(vb1.z, h, l); hb[16] = h; lb[16] = l;
                split_tf32(vb1.w, h, l); hb[24] = h; lb[24] = l;
            }
        }
        __syncthreads();

        // ---- prefetch next stage ----
        if (s + 1 < NSTAGE) {
            const int k0 = (s + 1) * GBK;
            va0 = *(const float4*)&Arow[k0 + akk];
            va1 = *(const float4*)&Arow[k0 + akk + 8];
            vb0 = *(const float4*)&W[(size_t)(k0 + bkk) * DM + bn + bcolb];
            vb1 = *(const float4*)&W[(size_t)(k0 + bkk + 8) * DM + bn + bcolb];
        }

        // ---- mma over the two k8-steps ----
#pragma unroll
        for (int ks = 0; ks < 2; ++ks) {
            uint4 Ah[4], Al[4];
            uint2 Bh[4], Bl[4];
#pragma unroll
            for (int i = 0; i < 4; ++i) {
                Ah[i] = *(const uint4*)&Asm[ks][wm * 4 + i][0][lane * 4];
                Al[i] = *(const uint4*)&Asm[ks][wm * 4 + i][1][lane * 4];
            }
#pragma unroll
            for (int j = 0; j < 4; ++j) {
                Bh[j] = *(const uint2*)&Bsm[ks][wn * 4 + j][0][lane * 2];
                Bl[j] = *(const uint2*)&Bsm[ks][wn * 4 + j][1][lane * 2];
            }
#pragma unroll
            for (int i = 0; i < 4; ++i)
#pragma unroll
                for (int j = 0; j < 4; ++j) {
                    mma_tf32(acc[i][j], Ah[i], Bh[j]);
                    mma_tf32(acc[i][j], Al[i], Bh[j]);
                    mma_tf32(acc[i][j], Ah[i], Bl[j]);
                }
        }
        __syncthreads();
    }

    // ---- epilogue: +bias, softplus, store ----
    const int g = lane >> 2, t = lane & 3;
#pragma unroll
    for (int i = 0; i < 4; ++i) {
        const int r0 = bm + wm * 64 + i * 16 + g;
#pragma unroll
        for (int j = 0; j < 4; ++j) {
            const int c = bn + wn * 32 + j * 8 + t * 2;
            const float b0 = bias[c], b1 = bias[c + 1];
            float2 v0, v1;
            v0.x = softplus_f(acc[i][j][0] + b0);
            v0.y = softplus_f(acc[i][j][1] + b1);
            v1.x = softplus_f(acc[i][j][2] + b0);
            v1.y = softplus_f(acc[i][j][3] + b1);
            *(float2*)&g_delta[(size_t)r0 * DM + c]       = v0;
            *(float2*)&g_delta[(size_t)(r0 + 8) * DM + c] = v1;
        }
    }
}

// ---------------- B/C projections, W slice cached in smem ----------------
// grid (4 output-groups of 8, 64 row-groups of 128); block 256.
#define BC_ROWS 128
__global__ __launch_bounds__(256)
void bc_kernel(const float* __restrict__ x, const float* __restrict__ bb,
               const float* __restrict__ bc) {
    __shared__ float Ws[8 * DM];   // 32 KB: 8 transposed weight rows
    __shared__ float xs[DM];       // 4 KB

    const int tid = threadIdx.x;
    const int og  = blockIdx.x;    // 0..3
    const int rg  = blockIdx.y;    // 0..63

    const float4* wsrc = (const float4*)(g_WT + (size_t)og * 8 * DM);
    float4* wdst = (float4*)Ws;
#pragma unroll
    for (int i = tid; i < 8 * DM / 4; i += 256) wdst[i] = wsrc[i];

    const int o    = tid >> 5;        // 0..7
    const int lane = tid & 31;
    const int oglob = og * 8 + o;
    const int n    = oglob & 15;
    const int comp = oglob >> 4;
    const float biasv = comp ? bc[n] : bb[n];
    float* out = (float*)g_BC;

    __syncthreads();

    for (int rr = 0; rr < BC_ROWS; ++rr) {
        const int row = rg * BC_ROWS + rr;
        ((float4*)xs)[tid] = ((const float4*)(x + (size_t)row * DM))[tid];
        __syncthreads();

        const float4* xv = (const float4*)xs;
        const float4* wv = (const float4*)(Ws + (size_t)o * DM);
        float p = 0.f;
#pragma unroll
        for (int i = 0; i < 8; ++i) {
            float4 a = xv[lane + i * 32];
            float4 w = wv[lane + i * 32];
            p += a.x * w.x + a.y * w.y + a.z * w.z + a.w * w.w;
        }
        p += __shfl_xor_sync(0xffffffffu, p, 16);
        p += __shfl_xor_sync(0xffffffffu, p, 8);
        p += __shfl_xor_sync(0xffffffffu, p, 4);
        p += __shfl_xor_sync(0xffffffffu, p, 2);
        p += __shfl_xor_sync(0xffffffffu, p, 1);
        if (lane == 0) out[((size_t)row * ST + n) * 2 + comp] = p + biasv;
        __syncthreads();   // protect xs before next iteration overwrites
    }
}

// ---------------- sequential scan: one thread per (b, d, n) ----------------
__global__ __launch_bounds__(128)
void scan_kernel(const float* __restrict__ x, const float* __restrict__ A_log,
                 const float* __restrict__ D_skip, float* __restrict__ y) {
    const int gw   = blockIdx.x * (blockDim.x >> 5) + (threadIdx.x >> 5); // 0..2047
    const int lane = threadIdx.x & 31;
    const int half = lane >> 4;
    const int n    = lane & 15;

    const int b     = gw >> 9;          // 512 warps per batch
    const int dpair = gw & 511;
    const int d     = dpair * 2 + half;

    const float A   = -__expf(A_log[d * ST + n]);   // negative
    const float dsk = D_skip[d];

    const float*  xp  = x       + (size_t)b * SEQ * DM + d;
    const float*  dp  = g_delta + (size_t)b * SEQ * DM + d;
    const float2* bcp = g_BC    + (size_t)b * SEQ * ST + n;
    float*        yp  = y       + (size_t)b * SEQ * DM + d;

    float h = 0.f;
#pragma unroll 4
    for (int t = 0; t < SEQ; ++t) {
        float  xv = xp[(size_t)t * DM];
        float  dt = dp[(size_t)t * DM];
        float2 bcv = bcp[(size_t)t * ST];
        float  bar = __expf(dt * A);                 // in (0,1]
        h = fmaf(bar, h, dt * xv * bcv.x);
        float p = h * bcv.y;
        p += __shfl_xor_sync(0xffffffffu, p, 8);
        p += __shfl_xor_sync(0xffffffffu, p, 4);
        p += __shfl_xor_sync(0xffffffffu, p, 2);
        p += __shfl_xor_sync(0xffffffffu, p, 1);
        if (n == 0) yp[(size_t)t * DM] = fmaf(xv, dsk, p);
    }
}

// ---------------- launch ----------------
extern "C" void kernel_launch(void* const* d_in, const int* in_sizes, int n_in,
                              void* d_out, int out_size) {
    (void)in_sizes; (void)n_in; (void)out_size;
    const float* x     = (const float*)d_in[0];
    const float* A_log = (const float*)d_in[1];
    const float* Dsk   = (const float*)d_in[2];
    const float* Wd    = (const float*)d_in[3];
    const float* bd    = (const float*)d_in[4];
    const float* Wb    = (const float*)d_in[5];
    const float* bb    = (const float*)d_in[6];
    const float* Wc    = (const float*)d_in[7];
    const float* bc    = (const float*)d_in[8];
    float* y = (float*)d_out;

    prep_wt_kernel<<<32, 1024>>>(Wb, Wc);
    gemm_tf32_softplus_kernel<<<dim3(DM / GBN, MROWS / GBM), 256>>>(x, Wd, bd);
    bc_kernel<<<dim3(4, 64), 256>>>(x, bb, bc);
    scan_kernel<<<512, 128>>>(x, A_log, Dsk, y);
}

// round 3
// speedup vs baseline: 1.2011x; 1.2011x over previous
#include <cuda_runtime.h>
#include <math.h>
#include <stdint.h>

#define B_SZ 4
#define SEQ 2048
#define DM 1024
#define ST 16
#define MROWS (B_SZ * SEQ)   // 8192

// ---------------- scratch (__device__ globals; no allocation allowed) ----------------
__device__ float  g_delta[MROWS * DM];      // softplus(x@Wd+bd), 32 MB
__device__ float2 g_BC[MROWS * ST];         // (B, C) interleaved per (row, n), 1 MB
__device__ float  g_WT[32 * DM];            // rows 0-15: Wb^T, rows 16-31: Wc^T

// ---------------- prep: transpose Wb, Wc into g_WT ----------------
__global__ void prep_wt_kernel(const float* __restrict__ Wb, const float* __restrict__ Wc) {
    int i = blockIdx.x * blockDim.x + threadIdx.x;   // 0 .. 32767
    if (i < ST * DM) {
        int col = i & 15, k = i >> 4;
        g_WT[col * DM + k] = Wb[i];
    } else {
        int j = i - ST * DM;
        int col = j & 15, k = j >> 4;
        g_WT[(16 + col) * DM + k] = Wc[j];
    }
}

// ================== TF32 tensor-core GEMM: delta = softplus(X @ Wd + bd) ==================
// 3xTF32 split: D = Ah*Bh + Al*Bh + Ah*Bl (~fp32 accuracy).
// Block tile 128x64, BK=16, 8 warps as 4M x 2N, warp tile 32x32.
// Smem holds fragments pre-permuted into m16n8k8 register order (layout verified in R2).

__device__ __forceinline__ void split_tf32(float v, float& hi, float& lo) {
    uint32_t h;
    asm("cvt.rna.tf32.f32 %0, %1;" : "=r"(h) : "f"(v));
    float hf = __uint_as_float(h);
    float l = v - hf;
    uint32_t lt;
    asm("cvt.rna.tf32.f32 %0, %1;" : "=r"(lt) : "f"(l));
    hi = hf; lo = __uint_as_float(lt);
}

__device__ __forceinline__ void mma_tf32(float* c, const uint4& a, const uint2& b) {
    asm volatile(
        "mma.sync.aligned.m16n8k8.row.col.f32.tf32.tf32.f32 "
        "{%0,%1,%2,%3},{%4,%5,%6,%7},{%8,%9},{%0,%1,%2,%3};\n"
        : "+f"(c[0]), "+f"(c[1]), "+f"(c[2]), "+f"(c[3])
        : "r"(a.x), "r"(a.y), "r"(a.z), "r"(a.w), "r"(b.x), "r"(b.y));
}

__device__ __forceinline__ float softplus_f(float z) {
    return fmaxf(z, 0.f) + log1pf(__expf(-fabsf(z)));
}

#define GBM 128
#define GBN 64
#define GBK 16   // 2 k8-steps per stage
#define NSTAGE (DM / GBK)   // 64

__global__ __launch_bounds__(256, 2)
void gemm_tf32_softplus_kernel(const float* __restrict__ X, const float* __restrict__ W,
                               const float* __restrict__ bias) {
    __shared__ float Asm[2][8][2][128];   // [ks][mtile][hi/lo][lane*4+r]  16 KB
    __shared__ float Bsm[2][8][2][64];    // [ks][ntile][hi/lo][lane*2+r]   8 KB

    const int tid  = threadIdx.x;
    const int lane = tid & 31;
    const int wid  = tid >> 5;        // 0..7
    const int wm   = wid >> 1;        // warp M (0..3), 32 rows each
    const int wn   = wid & 1;         // warp N (0..1), 32 cols each
    const int bm   = blockIdx.y * GBM;
    const int bn   = blockIdx.x * GBN;

    // A loader: row = tid>>1 (0..127), k base = (tid&1)*4, plus +8 in k
    const int arow = tid >> 1;
    const int akk  = (tid & 1) * 4;
    // B loader: k = tid>>4 (0..15), col base = (tid&15)*4
    const int bkk  = tid >> 4;
    const int bcolb = (tid & 15) * 4;

    float acc[2][4][4];
#pragma unroll
    for (int i = 0; i < 2; ++i)
#pragma unroll
        for (int j = 0; j < 4; ++j)
#pragma unroll
            for (int r = 0; r < 4; ++r) acc[i][j][r] = 0.f;

    const float* Arow = X + (size_t)(bm + arow) * DM;

    // prologue: load stage 0
    float4 va0 = *(const float4*)&Arow[akk];
    float4 va1 = *(const float4*)&Arow[akk + 8];
    float4 vb0 = *(const float4*)&W[(size_t)bkk * DM + bn + bcolb];

    for (int s = 0; s < NSTAGE; ++s) {
        // ---- STS with hi/lo split (fragment-order layout, verified correct in R2) ----
        {
            const int mt = arow >> 4, ml = arow & 15, g = ml & 7, rb0 = ml >> 3;
            {
                const int ks = akk >> 3, rb1 = (akk >> 2) & 1, r = rb0 + 2 * rb1;
                float* hb = &Asm[ks][mt][0][g * 16 + r];
                float* lb = &Asm[ks][mt][1][g * 16 + r];
                float h, l;
                split_tf32(va0.x, h, l); hb[0]  = h; lb[0]  = l;
                split_tf32(va0.y, h, l); hb[4]  = h; lb[4]  = l;
                split_tf32(va0.z, h, l); hb[8]  = h; lb[8]  = l;
                split_tf32(va0.w, h, l); hb[12] = h; lb[12] = l;
            }
            {
                const int kkb = akk + 8;
                const int ks = kkb >> 3, rb1 = (kkb >> 2) & 1, r = rb0 + 2 * rb1;
                float* hb = &Asm[ks][mt][0][g * 16 + r];
                float* lb = &Asm[ks][mt][1][g * 16 + r];
                float h, l;
                split_tf32(va1.x, h, l); hb[0]  = h; lb[0]  = l;
                split_tf32(va1.y, h, l); hb[4]  = h; lb[4]  = l;
                split_tf32(va1.z, h, l); hb[8]  = h; lb[8]  = l;
                split_tf32(va1.w, h, l); hb[12] = h; lb[12] = l;
            }
            // B: (bkk, bcolb..+3) -> Bsm[ks][nt][hl][nl*8 + t*2 + rb]
            const int nt = bcolb >> 3, nl0 = bcolb & 7;
            const int ks = bkk >> 3, kl = bkk & 7, t = kl & 3, rb = kl >> 2;
            float* hb = &Bsm[ks][nt][0][nl0 * 8 + t * 2 + rb];
            float* lb = &Bsm[ks][nt][1][nl0 * 8 + t * 2 + rb];
            float h, l;
            split_tf32(vb0.x, h, l); hb[0]  = h; lb[0]  = l;
            split_tf32(vb0.y, h, l); hb[8]  = h; lb[8]  = l;
            split_tf32(vb0.z, h, l); hb[16] = h; lb[16] = l;
            split_tf32(vb0.w, h, l); hb[24] = h; lb[24] = l;
        }
        __syncthreads();

        // ---- prefetch next stage ----
        if (s + 1 < NSTAGE) {
            const int k0 = (s + 1) * GBK;
            va0 = *(const float4*)&Arow[k0 + akk];
            va1 = *(const float4*)&Arow[k0 + akk + 8];
            vb0 = *(const float4*)&W[(size_t)(k0 + bkk) * DM + bn + bcolb];
        }

        // ---- mma over the two k8-steps ----
#pragma unroll
        for (int ks = 0; ks < 2; ++ks) {
            uint4 Ah[2], Al[2];
            uint2 Bh[4], Bl[4];
#pragma unroll
            for (int i = 0; i < 2; ++i) {
                Ah[i] = *(const uint4*)&Asm[ks][wm * 2 + i][0][lane * 4];
                Al[i] = *(const uint4*)&Asm[ks][wm * 2 + i][1][lane * 4];
            }
#pragma unroll
            for (int j = 0; j < 4; ++j) {
                Bh[j] = *(const uint2*)&Bsm[ks][wn * 4 + j][0][lane * 2];
                Bl[j] = *(const uint2*)&Bsm[ks][wn * 4 + j][1][lane * 2];
            }
#pragma unroll
            for (int i = 0; i < 2; ++i)
#pragma unroll
                for (int j = 0; j < 4; ++j) {
                    mma_tf32(acc[i][j], Ah[i], Bh[j]);
                    mma_tf32(acc[i][j], Al[i], Bh[j]);
                    mma_tf32(acc[i][j], Ah[i], Bl[j]);
                }
        }
        __syncthreads();
    }

    // ---- epilogue: +bias, softplus, store ----
    const int g = lane >> 2, t = lane & 3;
#pragma unroll
    for (int i = 0; i < 2; ++i) {
        const int r0 = bm + (wm * 2 + i) * 16 + g;
#pragma unroll
        for (int j = 0; j < 4; ++j) {
            const int c = bn + (wn * 4 + j) * 8 + t * 2;
            const float b0 = bias[c], b1 = bias[c + 1];
            float2 v0, v1;
            v0.x = softplus_f(acc[i][j][0] + b0);
            v0.y = softplus_f(acc[i][j][1] + b1);
            v1.x = softplus_f(acc[i][j][2] + b0);
            v1.y = softplus_f(acc[i][j][3] + b1);
            *(float2*)&g_delta[(size_t)r0 * DM + c]       = v0;
            *(float2*)&g_delta[(size_t)(r0 + 8) * DM + c] = v1;
        }
    }
}

// ---------------- B/C projections: 4 rows per block, weights streamed once ----------------
__global__ __launch_bounds__(128)
void bc_kernel(const float* __restrict__ x, const float* __restrict__ bb,
               const float* __restrict__ bc) {
    __shared__ float xs[4][DM];       // 16 KB
    __shared__ float red[4][4][32];   // [row][seg][o]

    const int tid  = threadIdx.x;     // 0..127
    const int row0 = blockIdx.x * 4;

    // load 4 rows of x (4096 floats = 1024 float4)
    const float4* xsrc = (const float4*)(x + (size_t)row0 * DM);
    float4* xdst = (float4*)xs;
#pragma unroll
    for (int k = 0; k < 8; ++k) xdst[tid + k * 128] = xsrc[tid + k * 128];
    __syncthreads();

    const int o   = tid & 31;   // output id: 0-15 -> B, 16-31 -> C
    const int seg = tid >> 5;   // K-segment 0..3

    const float4* w = (const float4*)(g_WT + (size_t)o * DM + seg * 256);
    float p0 = 0.f, p1 = 0.f, p2 = 0.f, p3 = 0.f;
#pragma unroll 8
    for (int i = 0; i < 64; ++i) {
        float4 ww = w[i];
        float4 a0 = ((const float4*)xs[0])[seg * 64 + i];
        float4 a1 = ((const float4*)xs[1])[seg * 64 + i];
        float4 a2 = ((const float4*)xs[2])[seg * 64 + i];
        float4 a3 = ((const float4*)xs[3])[seg * 64 + i];
        p0 += a0.x * ww.x + a0.y * ww.y + a0.z * ww.z + a0.w * ww.w;
        p1 += a1.x * ww.x + a1.y * ww.y + a1.z * ww.z + a1.w * ww.w;
        p2 += a2.x * ww.x + a2.y * ww.y + a2.z * ww.z + a2.w * ww.w;
        p3 += a3.x * ww.x + a3.y * ww.y + a3.z * ww.z + a3.w * ww.w;
    }
    red[0][seg][o] = p0;
    red[1][seg][o] = p1;
    red[2][seg][o] = p2;
    red[3][seg][o] = p3;
    __syncthreads();

    // tid -> (row r = tid>>5, output o = tid&31)
    {
        const int r = tid >> 5, oo = tid & 31;
        float s = red[r][0][oo] + red[r][1][oo] + red[r][2][oo] + red[r][3][oo];
        const int col = oo & 15, comp = oo >> 4;
        const float bias = comp ? bc[col] : bb[col];
        float* out = (float*)g_BC;
        out[((size_t)(row0 + r) * ST + col) * 2 + comp] = s + bias;
    }
}

// ---------------- sequential scan: one thread per (b, d, n) ----------------
__global__ __launch_bounds__(128)
void scan_kernel(const float* __restrict__ x, const float* __restrict__ A_log,
                 const float* __restrict__ D_skip, float* __restrict__ y) {
    const int gw   = blockIdx.x * (blockDim.x >> 5) + (threadIdx.x >> 5); // 0..2047
    const int lane = threadIdx.x & 31;
    const int half = lane >> 4;
    const int n    = lane & 15;

    const int b     = gw >> 9;
    const int dpair = gw & 511;
    const int d     = dpair * 2 + half;

    const float A   = -__expf(A_log[d * ST + n]);
    const float dsk = D_skip[d];

    const float*  xp  = x       + (size_t)b * SEQ * DM + d;
    const float*  dp  = g_delta + (size_t)b * SEQ * DM + d;
    const float2* bcp = g_BC    + (size_t)b * SEQ * ST + n;
    float*        yp  = y       + (size_t)b * SEQ * DM + d;

    float h = 0.f;
#pragma unroll 4
    for (int t = 0; t < SEQ; ++t) {
        float  xv = xp[(size_t)t * DM];
        float  dt = dp[(size_t)t * DM];
        float2 bcv = bcp[(size_t)t * ST];
        float  bar = __expf(dt * A);
        h = fmaf(bar, h, dt * xv * bcv.x);
        float p = h * bcv.y;
        p += __shfl_xor_sync(0xffffffffu, p, 8);
        p += __shfl_xor_sync(0xffffffffu, p, 4);
        p += __shfl_xor_sync(0xffffffffu, p, 2);
        p += __shfl_xor_sync(0xffffffffu, p, 1);
        if (n == 0) yp[(size_t)t * DM] = fmaf(xv, dsk, p);
    }
}

// ---------------- launch ----------------
extern "C" void kernel_launch(void* const* d_in, const int* in_sizes, int n_in,
                              void* d_out, int out_size) {
    (void)in_sizes; (void)n_in; (void)out_size;
    const float* x     = (const float*)d_in[0];
    const float* A_log = (const float*)d_in[1];
    const float* Dsk   = (const float*)d_in[2];
    const float* Wd    = (const float*)d_in[3];
    const float* bd    = (const float*)d_in[4];
    const float* Wb    = (const float*)d_in[5];
    const float* bb    = (const float*)d_in[6];
    const float* Wc    = (const float*)d_in[7];
    const float* bc    = (const float*)d_in[8];
    float* y = (float*)d_out;

    prep_wt_kernel<<<32, 1024>>>(Wb, Wc);
    gemm_tf32_softplus_kernel<<<dim3(DM / GBN, MROWS / GBM), 256>>>(x, Wd, bd);
    bc_kernel<<<MROWS / 4, 128>>>(x, bb, bc);
    scan_kernel<<<512, 128>>>(x, A_log, Dsk, y);
}

// round 5
// speedup vs baseline: 2.2521x; 1.8751x over previous
#include <cuda_runtime.h>
#include <math.h>
#include <stdint.h>

#define B_SZ 4
#define SEQ 2048
#define DM 1024
#define ST 16
#define MROWS (B_SZ * SEQ)   // 8192

// ---------------- scratch ----------------
__device__ float g_deltaT[DM * MROWS];     // delta transposed: [d][b*SEQ+t], 32 MB
__device__ float g_xT[DM * MROWS];         // x transposed, 32 MB
__device__ float g_yT[DM * MROWS];         // y transposed, 32 MB
__device__ float g_BT[B_SZ * ST * SEQ];    // B proj, [b][n][t]
__device__ float g_CT[B_SZ * ST * SEQ];    // C proj, [b][n][t]
__device__ float g_WT[32 * DM];            // rows 0-15: Wb^T, rows 16-31: Wc^T

// ---------------- prep: transpose Wb, Wc into g_WT ----------------
__global__ void prep_wt_kernel(const float* __restrict__ Wb, const float* __restrict__ Wc) {
    int i = blockIdx.x * blockDim.x + threadIdx.x;
    if (i < ST * DM) {
        int col = i & 15, k = i >> 4;
        g_WT[col * DM + k] = Wb[i];
    } else {
        int j = i - ST * DM;
        int col = j & 15, k = j >> 4;
        g_WT[(16 + col) * DM + k] = Wc[j];
    }
}

// ---------------- transpose x [MROWS,DM] -> g_xT [DM,MROWS] ----------------
__global__ __launch_bounds__(256)
void transpose_in_kernel(const float* __restrict__ in) {
    __shared__ float tile[32][33];
    const int c0 = blockIdx.x * 32, r0 = blockIdx.y * 32;
    const int tx = threadIdx.x, ty = threadIdx.y;  // 32 x 8
#pragma unroll
    for (int j = 0; j < 32; j += 8)
        tile[ty + j][tx] = in[(size_t)(r0 + ty + j) * DM + c0 + tx];
    __syncthreads();
#pragma unroll
    for (int j = 0; j < 32; j += 8)
        g_xT[(size_t)(c0 + ty + j) * MROWS + r0 + tx] = tile[tx][ty + j];
}

// ---------------- transpose g_yT [DM,MROWS] -> out [MROWS,DM] ----------------
__global__ __launch_bounds__(256)
void transpose_out_kernel(float* __restrict__ out) {
    __shared__ float tile[32][33];
    const int c0 = blockIdx.x * 32, r0 = blockIdx.y * 32;   // c0 over MROWS, r0 over DM
    const int tx = threadIdx.x, ty = threadIdx.y;
#pragma unroll
    for (int j = 0; j < 32; j += 8)
        tile[ty + j][tx] = g_yT[(size_t)(r0 + ty + j) * MROWS + c0 + tx];
    __syncthreads();
#pragma unroll
    for (int j = 0; j < 32; j += 8)
        out[(size_t)(c0 + ty + j) * DM + r0 + tx] = tile[tx][ty + j];
}

// ================== TF32 tensor-core GEMM: deltaT = softplus(X @ Wd + bd)^T ==================
__device__ __forceinline__ void split_tf32(float v, float& hi, float& lo) {
    uint32_t h;
    asm("cvt.rna.tf32.f32 %0, %1;" : "=r"(h) : "f"(v));
    float hf = __uint_as_float(h);
    float l = v - hf;
    uint32_t lt;
    asm("cvt.rna.tf32.f32 %0, %1;" : "=r"(lt) : "f"(l));
    hi = hf; lo = __uint_as_float(lt);
}

__device__ __forceinline__ void mma_tf32(float* c, const uint4& a, const uint2& b) {
    asm volatile(
        "mma.sync.aligned.m16n8k8.row.col.f32.tf32.tf32.f32 "
        "{%0,%1,%2,%3},{%4,%5,%6,%7},{%8,%9},{%0,%1,%2,%3};\n"
        : "+f"(c[0]), "+f"(c[1]), "+f"(c[2]), "+f"(c[3])
        : "r"(a.x), "r"(a.y), "r"(a.z), "r"(a.w), "r"(b.x), "r"(b.y));
}

__device__ __forceinline__ float softplus_f(float z) {
    return fmaxf(z, 0.f) + log1pf(__expf(-fabsf(z)));
}

#define GBM 128
#define GBN 64
#define GBK 16
#define NSTAGE (DM / GBK)   // 64

__global__ __launch_bounds__(256, 2)
void gemm_tf32_softplus_kernel(const float* __restrict__ X, const float* __restrict__ W,
                               const float* __restrict__ bias) {
    __shared__ float Asm[2][8][2][128];   // [ks][mtile][hi/lo][swizzled frag idx]
    __shared__ float Bsm[2][8][2][64];

    const int tid  = threadIdx.x;
    const int lane = tid & 31;
    const int wid  = tid >> 5;
    const int wm   = wid >> 1;        // 0..3
    const int wn   = wid & 1;         // 0..1
    const int bm   = blockIdx.y * GBM;
    const int bn   = blockIdx.x * GBN;

    const int arow = tid >> 1;
    const int akk  = (tid & 1) * 4;
    const int bkk  = tid >> 4;
    const int bcolb = (tid & 15) * 4;

    float acc[2][4][4];
#pragma unroll
    for (int i = 0; i < 2; ++i)
#pragma unroll
        for (int j = 0; j < 4; ++j)
#pragma unroll
            for (int r = 0; r < 4; ++r) acc[i][j][r] = 0.f;

    const float* Arow = X + (size_t)(bm + arow) * DM;

    float4 va0 = *(const float4*)&Arow[akk];
    float4 va1 = *(const float4*)&Arow[akk + 8];
    float4 vb0 = *(const float4*)&W[(size_t)bkk * DM + bn + bcolb];

    for (int s = 0; s < NSTAGE; ++s) {
        // ---- STS, fragment order, XOR-swizzled against bank conflicts ----
        {
            const int mt = arow >> 4, ml = arow & 15, g = ml & 7, rb0 = ml >> 3;
            const int sa = (g & 3);     // A chunk swizzle
            {
                const int ks = akk >> 3, rb1 = (akk >> 2) & 1, r = rb0 + 2 * rb1;
                float* hb = &Asm[ks][mt][0][g * 16 + r];
                float* lb = &Asm[ks][mt][1][g * 16 + r];
                float h, l;
                split_tf32(va0.x, h, l); hb[(0 ^ sa) * 4] = h; lb[(0 ^ sa) * 4] = l;
                split_tf32(va0.y, h, l); hb[(1 ^ sa) * 4] = h; lb[(1 ^ sa) * 4] = l;
                split_tf32(va0.z, h, l); hb[(2 ^ sa) * 4] = h; lb[(2 ^ sa) * 4] = l;
                split_tf32(va0.w, h, l); hb[(3 ^ sa) * 4] = h; lb[(3 ^ sa) * 4] = l;
            }
            {
                const int kkb = akk + 8;
                const int ks = kkb >> 3, rb1 = (kkb >> 2) & 1, r = rb0 + 2 * rb1;
                float* hb = &Asm[ks][mt][0][g * 16 + r];
                float* lb = &Asm[ks][mt][1][g * 16 + r];
                float h, l;
                split_tf32(va1.x, h, l); hb[(0 ^ sa) * 4] = h; lb[(0 ^ sa) * 4] = l;
                split_tf32(va1.y, h, l); hb[(1 ^ sa) * 4] = h; lb[(1 ^ sa) * 4] = l;
                split_tf32(va1.z, h, l); hb[(2 ^ sa) * 4] = h; lb[(2 ^ sa) * 4] = l;
                split_tf32(va1.w, h, l); hb[(3 ^ sa) * 4] = h; lb[(3 ^ sa) * 4] = l;
            }
            // B: chunk index (nl*4+t) ^ (nt<<1); float index = chunk*2 + rb
            const int nt = bcolb >> 3, nl0 = bcolb & 7;
            const int ks = bkk >> 3, kl = bkk & 7, t = kl & 3, rb = kl >> 2;
            const int sb = (nt & 7) << 1;
            float* hrow = &Bsm[ks][nt][0][0];
            float* lrow = &Bsm[ks][nt][1][0];
            float h, l;
            split_tf32(vb0.x, h, l); { int c = (((nl0 + 0) * 4 + t) ^ sb) * 2 + rb; hrow[c] = h; lrow[c] = l; }
            split_tf32(vb0.y, h, l); { int c = (((nl0 + 1) * 4 + t) ^ sb) * 2 + rb; hrow[c] = h; lrow[c] = l; }
            split_tf32(vb0.z, h, l); { int c = (((nl0 + 2) * 4 + t) ^ sb) * 2 + rb; hrow[c] = h; lrow[c] = l; }
            split_tf32(vb0.w, h, l); { int c = (((nl0 + 3) * 4 + t) ^ sb) * 2 + rb; hrow[c] = h; lrow[c] = l; }
        }
        __syncthreads();

        if (s + 1 < NSTAGE) {
            const int k0 = (s + 1) * GBK;
            va0 = *(const float4*)&Arow[k0 + akk];
            va1 = *(const float4*)&Arow[k0 + akk + 8];
            vb0 = *(const float4*)&W[(size_t)(k0 + bkk) * DM + bn + bcolb];
        }

        const int g = lane >> 2, t = lane & 3;
        const int achunk = (t ^ (g & 3)) * 4 + g * 16;
#pragma unroll
        for (int ks = 0; ks < 2; ++ks) {
            uint4 Ah[2], Al[2];
            uint2 Bh[4], Bl[4];
#pragma unroll
            for (int i = 0; i < 2; ++i) {
                Ah[i] = *(const uint4*)&Asm[ks][wm * 2 + i][0][achunk];
                Al[i] = *(const uint4*)&Asm[ks][wm * 2 + i][1][achunk];
            }
#pragma unroll
            for (int j = 0; j < 4; ++j) {
                const int ntj = wn * 4 + j;
                const int bc = (lane ^ ((ntj & 7) << 1)) * 2;
                Bh[j] = *(const uint2*)&Bsm[ks][ntj][0][bc];
                Bl[j] = *(const uint2*)&Bsm[ks][ntj][1][bc];
            }
#pragma unroll
            for (int i = 0; i < 2; ++i)
#pragma unroll
                for (int j = 0; j < 4; ++j) {
                    mma_tf32(acc[i][j], Ah[i], Bh[j]);
                    mma_tf32(acc[i][j], Al[i], Bh[j]);
                    mma_tf32(acc[i][j], Ah[i], Bl[j]);
                }
        }
        __syncthreads();
    }

    // ---- epilogue: +bias, softplus, store TRANSPOSED ----
    const int g = lane >> 2, t = lane & 3;
#pragma unroll
    for (int i = 0; i < 2; ++i) {
        const int r0 = bm + (wm * 2 + i) * 16 + g;
#pragma unroll
        for (int j = 0; j < 4; ++j) {
            const int c = bn + (wn * 4 + j) * 8 + t * 2;
            const float b0 = bias[c], b1 = bias[c + 1];
            g_deltaT[(size_t)c * MROWS + r0]           = softplus_f(acc[i][j][0] + b0);
            g_deltaT[(size_t)(c + 1) * MROWS + r0]     = softplus_f(acc[i][j][1] + b1);
            g_deltaT[(size_t)c * MROWS + r0 + 8]       = softplus_f(acc[i][j][2] + b0);
            g_deltaT[(size_t)(c + 1) * MROWS + r0 + 8] = softplus_f(acc[i][j][3] + b1);
        }
    }
}

// ---------------- B/C projections -> transposed g_BT/g_CT ----------------
__global__ __launch_bounds__(128)
void bc_kernel(const float* __restrict__ x, const float* __restrict__ bb,
               const float* __restrict__ bc) {
    __shared__ float xs[4][DM];
    __shared__ float red[4][4][32];

    const int tid  = threadIdx.x;
    const int row0 = blockIdx.x * 4;

    const float4* xsrc = (const float4*)(x + (size_t)row0 * DM);
    float4* xdst = (float4*)xs;
#pragma unroll
    for (int k = 0; k < 8; ++k) xdst[tid + k * 128] = xsrc[tid + k * 128];
    __syncthreads();

    const int o   = tid & 31;
    const int seg = tid >> 5;

    const float4* w = (const float4*)(g_WT + (size_t)o * DM + seg * 256);
    float p0 = 0.f, p1 = 0.f, p2 = 0.f, p3 = 0.f;
#pragma unroll 8
    for (int i = 0; i < 64; ++i) {
        float4 ww = w[i];
        float4 a0 = ((const float4*)xs[0])[seg * 64 + i];
        float4 a1 = ((const float4*)xs[1])[seg * 64 + i];
        float4 a2 = ((const float4*)xs[2])[seg * 64 + i];
        float4 a3 = ((const float4*)xs[3])[seg * 64 + i];
        p0 += a0.x * ww.x + a0.y * ww.y + a0.z * ww.z + a0.w * ww.w;
        p1 += a1.x * ww.x + a1.y * ww.y + a1.z * ww.z + a1.w * ww.w;
        p2 += a2.x * ww.x + a2.y * ww.y + a2.z * ww.z + a2.w * ww.w;
        p3 += a3.x * ww.x + a3.y * ww.y + a3.z * ww.z + a3.w * ww.w;
    }
    red[0][seg][o] = p0;
    red[1][seg][o] = p1;
    red[2][seg][o] = p2;
    red[3][seg][o] = p3;
    __syncthreads();

    {
        const int r = tid >> 5, oo = tid & 31;
        float s = red[r][0][oo] + red[r][1][oo] + red[r][2][oo] + red[r][3][oo];
        const int col = oo & 15, comp = oo >> 4;
        const float bias = comp ? bc[col] : bb[col];
        const int row = row0 + r;
        const int b = row >> 11, t = row & (SEQ - 1);
        float* dst = comp ? g_CT : g_BT;
        dst[((size_t)b * ST + col) * SEQ + t] = s + bias;
    }
}

// ---------------- scan v2: t-contiguous layouts, float4 loads over 4 timesteps ----------------
__global__ __launch_bounds__(256)
void scan2_kernel(const float* __restrict__ A_log, const float* __restrict__ D_skip) {
    const int gw   = blockIdx.x * 8 + (threadIdx.x >> 5);   // 0..2047
    const int lane = threadIdx.x & 31;
    const int half = lane >> 4;
    const int n    = lane & 15;

    const int b     = gw >> 9;
    const int dpair = gw & 511;
    const int d     = dpair * 2 + half;

    const float A   = -__expf(A_log[d * ST + n]);
    const float dsk = D_skip[d];

    const float* xp = g_xT     + (size_t)d * MROWS + b * SEQ;
    const float* dp = g_deltaT + (size_t)d * MROWS + b * SEQ;
    const float* Bp = g_BT     + ((size_t)b * ST + n) * SEQ;
    const float* Cp = g_CT     + ((size_t)b * ST + n) * SEQ;
    float*       yp = g_yT     + (size_t)d * MROWS + b * SEQ;

    float h = 0.f;
    for (int t0 = 0; t0 < SEQ; t0 += 4) {
        float4 xv4 = *(const float4*)(xp + t0);
        float4 dt4 = *(const float4*)(dp + t0);
        float4 bv4 = *(const float4*)(Bp + t0);
        float4 cv4 = *(const float4*)(Cp + t0);
        float yv[4];
        const float xs[4] = {xv4.x, xv4.y, xv4.z, xv4.w};
        const float ds[4] = {dt4.x, dt4.y, dt4.z, dt4.w};
        const float bs[4] = {bv4.x, bv4.y, bv4.z, bv4.w};
        const float cs[4] = {cv4.x, cv4.y, cv4.z, cv4.w};
#pragma unroll
        for (int j = 0; j < 4; ++j) {
            const float bar = __expf(ds[j] * A);
            h = fmaf(bar, h, ds[j] * xs[j] * bs[j]);
            float p = h * cs[j];
            p += __shfl_xor_sync(0xffffffffu, p, 8);
            p += __shfl_xor_sync(0xffffffffu, p, 4);
            p += __shfl_xor_sync(0xffffffffu, p, 2);
            p += __shfl_xor_sync(0xffffffffu, p, 1);
            yv[j] = fmaf(xs[j], dsk, p);
        }
        if (n == 0) *(float4*)(yp + t0) = make_float4(yv[0], yv[1], yv[2], yv[3]);
    }
}

// ---------------- launch ----------------
extern "C" void kernel_launch(void* const* d_in, const int* in_sizes, int n_in,
                              void* d_out, int out_size) {
    (void)in_sizes; (void)n_in; (void)out_size;
    const float* x     = (const float*)d_in[0];
    const float* A_log = (const float*)d_in[1];
    const float* Dsk   = (const float*)d_in[2];
    const float* Wd    = (const float*)d_in[3];
    const float* bd    = (const float*)d_in[4];
    const float* Wb    = (const float*)d_in[5];
    const float* bb    = (const float*)d_in[6];
    const float* Wc    = (const float*)d_in[7];
    const float* bc    = (const float*)d_in[8];
    float* y = (float*)d_out;

    prep_wt_kernel<<<32, 1024>>>(Wb, Wc);
    transpose_in_kernel<<<dim3(DM / 32, MROWS / 32), dim3(32, 8)>>>(x);
    gemm_tf32_softplus_kernel<<<dim3(DM / GBN, MROWS / GBM), 256>>>(x, Wd, bd);
    bc_kernel<<<MROWS / 4, 128>>>(x, bb, bc);
    scan2_kernel<<<256, 256>>>(A_log, Dsk);
    transpose_out_kernel<<<dim3(MROWS / 32, DM / 32), dim3(32, 8)>>>(y);
}

// round 7
// speedup vs baseline: 2.3334x; 1.0361x over previous
#include <cuda_runtime.h>
#include <cuda_bf16.h>
#include <math.h>
#include <stdint.h>

#define B_SZ 4
#define SEQ 2048
#define DM 1024
#define ST 16
#define MROWS (B_SZ * SEQ)   // 8192

// ---------------- scratch ----------------
__device__ __nv_bfloat16 g_Xh[MROWS * DM];    // X hi, 16 MB
__device__ __nv_bfloat16 g_Xl[MROWS * DM];    // X lo residual
__device__ __nv_bfloat16 g_Wh[DM * DM];       // Wd^T hi  [n][k]
__device__ __nv_bfloat16 g_Wl[DM * DM];       // Wd^T lo
__device__ __nv_bfloat16 g_WBCh[32 * DM];     // [Wb^T ; Wc^T] hi  [n][k]
__device__ __nv_bfloat16 g_WBCl[32 * DM];     // lo
__device__ float  g_deltaT[DM * MROWS];       // delta transposed [d][b*SEQ+t]
__device__ float  g_xT[DM * MROWS];           // x transposed
__device__ float2 g_BC[MROWS * ST];           // (B,C) per (b*SEQ+t, n)

// ---------------- small helpers ----------------
__device__ __forceinline__ uint32_t smem_u32(const void* p) {
    uint32_t a;
    asm("{ .reg .u64 t; cvta.to.shared.u64 t, %1; cvt.u32.u64 %0, t; }" : "=r"(a) : "l"(p));
    return a;
}
__device__ __forceinline__ void ldsm_x4(uint32_t* r, uint32_t a) {
    asm volatile("ldmatrix.sync.aligned.m8n8.x4.shared.b16 {%0,%1,%2,%3}, [%4];"
                 : "=r"(r[0]), "=r"(r[1]), "=r"(r[2]), "=r"(r[3]) : "r"(a));
}
__device__ __forceinline__ void mma_bf16(float* c, const uint32_t* a, const uint32_t* b) {
    asm volatile("mma.sync.aligned.m16n8k16.row.col.f32.bf16.bf16.f32 "
                 "{%0,%1,%2,%3},{%4,%5,%6,%7},{%8,%9},{%0,%1,%2,%3};"
                 : "+f"(c[0]), "+f"(c[1]), "+f"(c[2]), "+f"(c[3])
                 : "r"(a[0]), "r"(a[1]), "r"(a[2]), "r"(a[3]), "r"(b[0]), "r"(b[1]));
}
__device__ __forceinline__ float softplus_f(float z) {
    return fmaxf(z, 0.f) + log1pf(__expf(-fabsf(z)));
}
// 16B-chunk index in a 4-chunk-per-row tile, XOR swizzle (conflict-free for STS.128 + ldmatrix)
#define SWC(row, c) (((row) * 4 + ((c) ^ (((row) >> 1) & 3))) * 16)

// ---------------- prep: split x into bf16 hi/lo ----------------
__global__ __launch_bounds__(256)
void split_x_kernel(const float* __restrict__ x) {
    int i = blockIdx.x * 256 + threadIdx.x;   // over MROWS*DM/4
    float4 v = ((const float4*)x)[i];
    __nv_bfloat16 h0 = __float2bfloat16_rn(v.x), h1 = __float2bfloat16_rn(v.y);
    __nv_bfloat16 h2 = __float2bfloat16_rn(v.z), h3 = __float2bfloat16_rn(v.w);
    __nv_bfloat16 l0 = __float2bfloat16_rn(v.x - __bfloat162float(h0));
    __nv_bfloat16 l1 = __float2bfloat16_rn(v.y - __bfloat162float(h1));
    __nv_bfloat16 l2 = __float2bfloat16_rn(v.z - __bfloat162float(h2));
    __nv_bfloat16 l3 = __float2bfloat16_rn(v.w - __bfloat162float(h3));
    __nv_bfloat162* ph = (__nv_bfloat162*)&g_Xh[(size_t)i * 4];
    __nv_bfloat162* pl = (__nv_bfloat162*)&g_Xl[(size_t)i * 4];
    ph[0] = {h0, h1}; ph[1] = {h2, h3};
    pl[0] = {l0, l1}; pl[1] = {l2, l3};
}

// ---------------- prep: split + transpose Wd -> g_Wh/g_Wl [n][k] ----------------
__global__ __launch_bounds__(256)
void split_wt_kernel(const float* __restrict__ W) {
    __shared__ float tile[32][33];
    const int n0 = blockIdx.x * 32, k0 = blockIdx.y * 32;
    const int tx = threadIdx.x, ty = threadIdx.y;   // 32 x 8
#pragma unroll
    for (int j = 0; j < 32; j += 8)
        tile[ty + j][tx] = W[(size_t)(k0 + ty + j) * DM + n0 + tx];
    __syncthreads();
#pragma unroll
    for (int j = 0; j < 32; j += 8) {
        const int n = n0 + ty + j, k = k0 + tx;
        float v = tile[tx][ty + j];
        __nv_bfloat16 h = __float2bfloat16_rn(v);
        __nv_bfloat16 l = __float2bfloat16_rn(v - __bfloat162float(h));
        g_Wh[(size_t)n * DM + k] = h;
        g_Wl[(size_t)n * DM + k] = l;
    }
}

// ---------------- prep: split + transpose Wb, Wc -> g_WBCh/l [32][DM] ----------------
__global__ __launch_bounds__(256)
void split_wbc_kernel(const float* __restrict__ Wb, const float* __restrict__ Wc) {
    int i = blockIdx.x * 256 + threadIdx.x;   // 0..32767
    float v; int row, k;
    if (i < ST * DM) {
        row = i & 15; k = i >> 4; v = Wb[i];
    } else {
        int j = i - ST * DM;
        row = 16 + (j & 15); k = j >> 4; v = Wc[j];
    }
    __nv_bfloat16 h = __float2bfloat16_rn(v);
    __nv_bfloat16 l = __float2bfloat16_rn(v - __bfloat162float(h));
    g_WBCh[(size_t)row * DM + k] = h;
    g_WBCl[(size_t)row * DM + k] = l;
}

// ---------------- transpose x [MROWS,DM] -> g_xT [DM,MROWS] ----------------
__global__ __launch_bounds__(256)
void transpose_in_kernel(const float* __restrict__ in) {
    __shared__ float tile[32][33];
    const int c0 = blockIdx.x * 32, r0 = blockIdx.y * 32;
    const int tx = threadIdx.x, ty = threadIdx.y;
#pragma unroll
    for (int j = 0; j < 32; j += 8)
        tile[ty + j][tx] = in[(size_t)(r0 + ty + j) * DM + c0 + tx];
    __syncthreads();
#pragma unroll
    for (int j = 0; j < 32; j += 8)
        g_xT[(size_t)(c0 + ty + j) * MROWS + r0 + tx] = tile[tx][ty + j];
}

// ================== bf16-split mma GEMM: deltaT = softplus(X @ Wd + bd)^T ==================
// Block 128x64, BK=32. 8 warps = 4M x 2N, warp tile 32x32. 3 products (AhBh+AlBh+AhBl).
__global__ __launch_bounds__(256, 2)
void gemm_main_kernel(const float* __restrict__ bias) {
    __shared__ __nv_bfloat16 sAh[128 * 32], sAl[128 * 32];   // 8 KB each
    __shared__ __nv_bfloat16 sBh[64 * 32],  sBl[64 * 32];    // 4 KB each

    const int tid = threadIdx.x, lane = tid & 31, wid = tid >> 5;
    const int wm = wid & 3, wn = wid >> 2;
    const int bm = blockIdx.y * 128, bn = blockIdx.x * 64;

    // loader: A 512 chunks x2 per buffer (2 per thread), B 256 chunks (1 per thread)
    const int r1 = tid >> 2, c1 = tid & 3;        // A rows 0..63 / B rows 0..63
    const uint32_t aAh = smem_u32(sAh), aAl = smem_u32(sAl);
    const uint32_t aBh = smem_u32(sBh), aBl = smem_u32(sBl);

    // ldmatrix lane addressing
    const int sub = lane >> 3;
    const int la_r  = wm * 32 + (sub & 1) * 8 + (lane & 7);   // + i*16
    const int la_c8 = sub >> 1;                                // k8 within k16
    const int lb_n  = wn * 32 + (sub >> 1) * 8 + (lane & 7);  // + p*16
    const int lb_c8 = sub & 1;

    float acc[2][4][4];
#pragma unroll
    for (int i = 0; i < 2; ++i)
#pragma unroll
        for (int j = 0; j < 4; ++j)
#pragma unroll
            for (int r = 0; r < 4; ++r) acc[i][j][r] = 0.f;

    const __nv_bfloat16* Ah0 = g_Xh + (size_t)(bm + r1) * DM;
    const __nv_bfloat16* Ah1 = g_Xh + (size_t)(bm + 64 + r1) * DM;
    const __nv_bfloat16* Al0 = g_Xl + (size_t)(bm + r1) * DM;
    const __nv_bfloat16* Al1 = g_Xl + (size_t)(bm + 64 + r1) * DM;
    const __nv_bfloat16* Bh0 = g_Wh + (size_t)(bn + r1) * DM;
    const __nv_bfloat16* Bl0 = g_Wl + (size_t)(bn + r1) * DM;

    uint4 pAh0 = *(const uint4*)(Ah0 + c1 * 8);
    uint4 pAh1 = *(const uint4*)(Ah1 + c1 * 8);
    uint4 pAl0 = *(const uint4*)(Al0 + c1 * 8);
    uint4 pAl1 = *(const uint4*)(Al1 + c1 * 8);
    uint4 pBh  = *(const uint4*)(Bh0 + c1 * 8);
    uint4 pBl  = *(const uint4*)(Bl0 + c1 * 8);

    for (int s = 0; s < 32; ++s) {
        *(uint4*)((char*)sAh + SWC(r1, c1))      = pAh0;
        *(uint4*)((char*)sAh + SWC(64 + r1, c1)) = pAh1;
        *(uint4*)((char*)sAl + SWC(r1, c1))      = pAl0;
        *(uint4*)((char*)sAl + SWC(64 + r1, c1)) = pAl1;
        *(uint4*)((char*)sBh + SWC(r1, c1))      = pBh;
        *(uint4*)((char*)sBl + SWC(r1, c1))      = pBl;
        __syncthreads();

        if (s + 1 < 32) {
            const int k0 = (s + 1) * 32;
            pAh0 = *(const uint4*)(Ah0 + k0 + c1 * 8);
            pAh1 = *(const uint4*)(Ah1 + k0 + c1 * 8);
            pAl0 = *(const uint4*)(Al0 + k0 + c1 * 8);
            pAl1 = *(const uint4*)(Al1 + k0 + c1 * 8);
            pBh  = *(const uint4*)(Bh0 + k0 + c1 * 8);
            pBl  = *(const uint4*)(Bl0 + k0 + c1 * 8);
        }

#pragma unroll
        for (int kh = 0; kh < 2; ++kh) {
            uint32_t Afh[2][4], Afl[2][4], Bfh[2][4], Bfl[2][4];
#pragma unroll
            for (int i = 0; i < 2; ++i) {
                ldsm_x4(Afh[i], aAh + SWC(la_r + i * 16, kh * 2 + la_c8));
                ldsm_x4(Afl[i], aAl + SWC(la_r + i * 16, kh * 2 + la_c8));
            }
#pragma unroll
            for (int p = 0; p < 2; ++p) {
                ldsm_x4(Bfh[p], aBh + SWC(lb_n + p * 16, kh * 2 + lb_c8));
                ldsm_x4(Bfl[p], aBl + SWC(lb_n + p * 16, kh * 2 + lb_c8));
            }
#pragma unroll
            for (int i = 0; i < 2; ++i)
#pragma unroll
                for (int j = 0; j < 4; ++j) {
                    const uint32_t* bh = &Bfh[j >> 1][(j & 1) * 2];
                    const uint32_t* bl = &Bfl[j >> 1][(j & 1) * 2];
                    mma_bf16(acc[i][j], Afh[i], bh);
                    mma_bf16(acc[i][j], Afl[i], bh);
                    mma_bf16(acc[i][j], Afh[i], bl);
                }
        }
        __syncthreads();
    }

    // epilogue: +bias, softplus, transposed store
    const int g = lane >> 2, t = lane & 3;
#pragma unroll
    for (int i = 0; i < 2; ++i) {
        const int row = bm + wm * 32 + i * 16 + g;
#pragma unroll
        for (int j = 0; j < 4; ++j) {
            const int col = bn + wn * 32 + j * 8 + t * 2;
            const float b0 = bias[col], b1 = bias[col + 1];
            g_deltaT[(size_t)col * MROWS + row]           = softplus_f(acc[i][j][0] + b0);
            g_deltaT[(size_t)(col + 1) * MROWS + row]     = softplus_f(acc[i][j][1] + b1);
            g_deltaT[(size_t)col * MROWS + row + 8]       = softplus_f(acc[i][j][2] + b0);
            g_deltaT[(size_t)(col + 1) * MROWS + row + 8] = softplus_f(acc[i][j][3] + b1);
        }
    }
}

// ================== bf16-split mma GEMM for B/C: [X @ (Wb||Wc)] -> g_BC ==================
// Block 128x32 (full N). 8 warps = 4M x 2N, warp tile 32x16.
__global__ __launch_bounds__(256, 2)
void gemm_bc_kernel(const float* __restrict__ bb, const float* __restrict__ bc) {
    __shared__ __nv_bfloat16 sAh[128 * 32], sAl[128 * 32];   // 8 KB each
    __shared__ __nv_bfloat16 sBh[32 * 32],  sBl[32 * 32];    // 2 KB each

    const int tid = threadIdx.x, lane = tid & 31, wid = tid >> 5;
    const int wm = wid & 3, wn = wid >> 2;
    const int bm = blockIdx.x * 128;

    const int r1 = tid >> 2, c1 = tid & 3;
    const int tb = tid & 127;
    const int rB = tb >> 2, cB = tb & 3;
    const uint32_t aAh = smem_u32(sAh), aAl = smem_u32(sAl);
    const uint32_t aBh = smem_u32(sBh), aBl = smem_u32(sBl);

    const int sub = lane >> 3;
    const int la_r  = wm * 32 + (sub & 1) * 8 + (lane & 7);
    const int la_c8 = sub >> 1;
    const int lb_n  = wn * 16 + (sub >> 1) * 8 + (lane & 7);
    const int lb_c8 = sub & 1;

    float acc[2][2][4];
#pragma unroll
    for (int i = 0; i < 2; ++i)
#pragma unroll
        for (int j = 0; j < 2; ++j)
#pragma unroll
            for (int r = 0; r < 4; ++r) acc[i][j][r] = 0.f;

    const __nv_bfloat16* Ah0 = g_Xh + (size_t)(bm + r1) * DM;
    const __nv_bfloat16* Ah1 = g_Xh + (size_t)(bm + 64 + r1) * DM;
    const __nv_bfloat16* Al0 = g_Xl + (size_t)(bm + r1) * DM;
    const __nv_bfloat16* Al1 = g_Xl + (size_t)(bm + 64 + r1) * DM;
    const __nv_bfloat16* Bsrc = ((tid < 128) ? g_WBCh : g_WBCl) + (size_t)rB * DM;
    char* sBdst = (char*)((tid < 128) ? sBh : sBl);

    uint4 pAh0 = *(const uint4*)(Ah0 + c1 * 8);
    uint4 pAh1 = *(const uint4*)(Ah1 + c1 * 8);
    uint4 pAl0 = *(const uint4*)(Al0 + c1 * 8);
    uint4 pAl1 = *(const uint4*)(Al1 + c1 * 8);
    uint4 pB   = *(const uint4*)(Bsrc + cB * 8);

    for (int s = 0; s < 32; ++s) {
        *(uint4*)((char*)sAh + SWC(r1, c1))      = pAh0;
        *(uint4*)((char*)sAh + SWC(64 + r1, c1)) = pAh1;
        *(uint4*)((char*)sAl + SWC(r1, c1))      = pAl0;
        *(uint4*)((char*)sAl + SWC(64 + r1, c1)) = pAl1;
        *(uint4*)(sBdst + SWC(rB, cB))           = pB;
        __syncthreads();

        if (s + 1 < 32) {
            const int k0 = (s + 1) * 32;
            pAh0 = *(const uint4*)(Ah0 + k0 + c1 * 8);
            pAh1 = *(const uint4*)(Ah1 + k0 + c1 * 8);
            pAl0 = *(const uint4*)(Al0 + k0 + c1 * 8);
            pAl1 = *(const uint4*)(Al1 + k0 + c1 * 8);
            pB   = *(const uint4*)(Bsrc + k0 + cB * 8);
        }

#pragma unroll
        for (int kh = 0; kh < 2; ++kh) {
            uint32_t Afh[2][4], Afl[2][4], Bfh[4], Bfl[4];
#pragma unroll
            for (int i = 0; i < 2; ++i) {
                ldsm_x4(Afh[i], aAh + SWC(la_r + i * 16, kh * 2 + la_c8));
                ldsm_x4(Afl[i], aAl + SWC(la_r + i * 16, kh * 2 + la_c8));
            }
            ldsm_x4(Bfh, aBh + SWC(lb_n, kh * 2 + lb_c8));
            ldsm_x4(Bfl, aBl + SWC(lb_n, kh * 2 + lb_c8));
#pragma unroll
            for (int i = 0; i < 2; ++i)
#pragma unroll
                for (int j = 0; j < 2; ++j) {
                    mma_bf16(acc[i][j], Afh[i], &Bfh[j * 2]);
                    mma_bf16(acc[i][j], Afl[i], &Bfh[j * 2]);
                    mma_bf16(acc[i][j], Afh[i], &Bfl[j * 2]);
                }
        }
        __syncthreads();
    }

    // epilogue -> g_BC interleaved: cols 0-15 = B (comp 0), 16-31 = C (comp 1)
    const int g = lane >> 2, t = lane & 3;
    float* out = (float*)g_BC;
#pragma unroll
    for (int i = 0; i < 2; ++i) {
        const int row = bm + wm * 32 + i * 16 + g;
#pragma unroll
        for (int j = 0; j < 2; ++j) {
            const int n0 = j * 8 + t * 2;     // 0..14
            const float bv0 = wn ? bc[n0] : bb[n0];
            const float bv1 = wn ? bc[n0 + 1] : bb[n0 + 1];
            out[((size_t)row * ST + n0) * 2 + wn]           = acc[i][j][0] + bv0;
            out[((size_t)row * ST + n0 + 1) * 2 + wn]       = acc[i][j][1] + bv1;
            out[((size_t)(row + 8) * ST + n0) * 2 + wn]     = acc[i][j][2] + bv0;
            out[((size_t)(row + 8) * ST + n0 + 1) * 2 + wn] = acc[i][j][3] + bv1;
        }
    }
}

// ---------------- scan: t-contiguous x/delta, coalesced BC, direct y store ----------------
__global__ __launch_bounds__(256)
void scan3_kernel(const float* __restrict__ A_log, const float* __restrict__ D_skip,
                  float* __restrict__ y) {
    const int gw   = blockIdx.x * 8 + (threadIdx.x >> 5);   // 0..2047
    const int lane = threadIdx.x & 31;
    const int half = lane >> 4;
    const int n    = lane & 15;

    const int b     = gw >> 9;
    const int dpair = gw & 511;
    const int d     = dpair * 2 + half;

    const float A   = -__expf(A_log[d * ST + n]);
    const float dsk = D_skip[d];

    const float*  xp  = g_xT     + (size_t)d * MROWS + b * SEQ;
    const float*  dp  = g_deltaT + (size_t)d * MROWS + b * SEQ;
    const float2* bcp = g_BC     + (size_t)b * SEQ * ST + n;
    float*        yp  = y        + ((size_t)b * SEQ) * DM + d;

    float h = 0.f;
    for (int t0 = 0; t0 < SEQ; t0 += 4) {
        float4 xv4 = *(const float4*)(xp + t0);
        float4 dt4 = *(const float4*)(dp + t0);
        const float xs[4] = {xv4.x, xv4.y, xv4.z, xv4.w};
        const float ds[4] = {dt4.x, dt4.y, dt4.z, dt4.w};
#pragma unroll
        for (int j = 0; j < 4; ++j) {
            const float2 bcv = bcp[(size_t)(t0 + j) * ST];
            const float bar = __expf(ds[j] * A);
            h = fmaf(bar, h, ds[j] * xs[j] * bcv.x);
            float p = h * bcv.y;
            p += __shfl_xor_sync(0xffffffffu, p, 8);
            p += __shfl_xor_sync(0xffffffffu, p, 4);
            p += __shfl_xor_sync(0xffffffffu, p, 2);
            p += __shfl_xor_sync(0xffffffffu, p, 1);
            if (n == 0) yp[(size_t)(t0 + j) * DM] = fmaf(xs[j], dsk, p);
        }
    }
}

// ---------------- launch ----------------
extern "C" void kernel_launch(void* const* d_in, const int* in_sizes, int n_in,
                              void* d_out, int out_size) {
    (void)in_sizes; (void)n_in; (void)out_size;
    const float* x     = (const float*)d_in[0];
    const float* A_log = (const float*)d_in[1];
    const float* Dsk   = (const float*)d_in[2];
    const float* Wd    = (const float*)d_in[3];
    const float* bd    = (const float*)d_in[4];
    const float* Wb    = (const float*)d_in[5];
    const float* bb    = (const float*)d_in[6];
    const float* Wc    = (const float*)d_in[7];
    const float* bc    = (const float*)d_in[8];
    float* y = (float*)d_out;

    split_x_kernel<<<MROWS * DM / 4 / 256, 256>>>(x);
    split_wt_kernel<<<dim3(32, 32), dim3(32, 8)>>>(Wd);
    split_wbc_kernel<<<2 * ST * DM / 256, 256>>>(Wb, Wc);
    transpose_in_kernel<<<dim3(DM / 32, MROWS / 32), dim3(32, 8)>>>(x);
    gemm_main_kernel<<<dim3(DM / 64, MROWS / 128), 256>>>(bd);
    gemm_bc_kernel<<<MROWS / 128, 256>>>(bb, bc);
    scan3_kernel<<<256, 256>>>(A_log, Dsk, y);
}

// round 9
// speedup vs baseline: 4.7563x; 2.0384x over previous
#include <cuda_runtime.h>
#include <cuda_bf16.h>
#include <math.h>
#include <stdint.h>

#define B_SZ 4
#define SEQ 2048
#define DM 1024
#define ST 16
#define MROWS (B_SZ * SEQ)   // 8192

// ---------------- scratch ----------------
__device__ __nv_bfloat16 g_Xh[MROWS * DM];    // X hi, 16 MB
__device__ __nv_bfloat16 g_Xl[MROWS * DM];    // X lo residual
__device__ __nv_bfloat16 g_Wh[DM * DM];       // Wd^T hi  [n][k]
__device__ __nv_bfloat16 g_Wl[DM * DM];       // Wd^T lo
__device__ __nv_bfloat16 g_WBCh[32 * DM];     // [Wb^T ; Wc^T] hi  [n][k]
__device__ __nv_bfloat16 g_WBCl[32 * DM];     // lo
__device__ float  g_deltaT[DM * MROWS];       // delta transposed [d][b*SEQ+t]
__device__ float  g_xT[DM * MROWS];           // x transposed
__device__ float2 g_BC[MROWS * ST];           // (B,C) per (b*SEQ+t, n)

// ---------------- small helpers ----------------
__device__ __forceinline__ uint32_t smem_u32(const void* p) {
    uint32_t a;
    asm("{ .reg .u64 t; cvta.to.shared.u64 t, %1; cvt.u32.u64 %0, t; }" : "=r"(a) : "l"(p));
    return a;
}
__device__ __forceinline__ void ldsm_x4(uint32_t* r, uint32_t a) {
    asm volatile("ldmatrix.sync.aligned.m8n8.x4.shared.b16 {%0,%1,%2,%3}, [%4];"
                 : "=r"(r[0]), "=r"(r[1]), "=r"(r[2]), "=r"(r[3]) : "r"(a));
}
__device__ __forceinline__ void mma_bf16(float* c, const uint32_t* a, const uint32_t* b) {
    asm volatile("mma.sync.aligned.m16n8k16.row.col.f32.bf16.bf16.f32 "
                 "{%0,%1,%2,%3},{%4,%5,%6,%7},{%8,%9},{%0,%1,%2,%3};"
                 : "+f"(c[0]), "+f"(c[1]), "+f"(c[2]), "+f"(c[3])
                 : "r"(a[0]), "r"(a[1]), "r"(a[2]), "r"(a[3]), "r"(b[0]), "r"(b[1]));
}
__device__ __forceinline__ void cp16(uint32_t dst, const void* src) {
    asm volatile("cp.async.cg.shared.global [%0], [%1], 16;" :: "r"(dst), "l"(src));
}
#define CP_COMMIT() asm volatile("cp.async.commit_group;")
#define CP_WAIT1()  asm volatile("cp.async.wait_group 1;")
__device__ __forceinline__ float softplus_f(float z) {
    return fmaxf(z, 0.f) + log1pf(__expf(-fabsf(z)));
}
// 16B-chunk offset in a 4-chunk-per-row tile, XOR swizzle (verified R7)
#define SWC(row, c) (((row) * 4 + ((c) ^ (((row) >> 1) & 3))) * 16)

// ---------------- prep: split x into bf16 hi/lo ----------------
__global__ __launch_bounds__(256)
void split_x_kernel(const float* __restrict__ x) {
    int i = blockIdx.x * 256 + threadIdx.x;   // over MROWS*DM/4
    float4 v = ((const float4*)x)[i];
    __nv_bfloat16 h0 = __float2bfloat16_rn(v.x), h1 = __float2bfloat16_rn(v.y);
    __nv_bfloat16 h2 = __float2bfloat16_rn(v.z), h3 = __float2bfloat16_rn(v.w);
    __nv_bfloat16 l0 = __float2bfloat16_rn(v.x - __bfloat162float(h0));
    __nv_bfloat16 l1 = __float2bfloat16_rn(v.y - __bfloat162float(h1));
    __nv_bfloat16 l2 = __float2bfloat16_rn(v.z - __bfloat162float(h2));
    __nv_bfloat16 l3 = __float2bfloat16_rn(v.w - __bfloat162float(h3));
    __nv_bfloat162* ph = (__nv_bfloat162*)&g_Xh[(size_t)i * 4];
    __nv_bfloat162* pl = (__nv_bfloat162*)&g_Xl[(size_t)i * 4];
    ph[0] = {h0, h1}; ph[1] = {h2, h3};
    pl[0] = {l0, l1}; pl[1] = {l2, l3};
}

// ---------------- prep: split + transpose Wd -> g_Wh/g_Wl [n][k] ----------------
__global__ __launch_bounds__(256)
void split_wt_kernel(const float* __restrict__ W) {
    __shared__ float tile[32][33];
    const int n0 = blockIdx.x * 32, k0 = blockIdx.y * 32;
    const int tx = threadIdx.x, ty = threadIdx.y;   // 32 x 8
#pragma unroll
    for (int j = 0; j < 32; j += 8)
        tile[ty + j][tx] = W[(size_t)(k0 + ty + j) * DM + n0 + tx];
    __syncthreads();
#pragma unroll
    for (int j = 0; j < 32; j += 8) {
        const int n = n0 + ty + j, k = k0 + tx;
        float v = tile[tx][ty + j];
        __nv_bfloat16 h = __float2bfloat16_rn(v);
        __nv_bfloat16 l = __float2bfloat16_rn(v - __bfloat162float(h));
        g_Wh[(size_t)n * DM + k] = h;
        g_Wl[(size_t)n * DM + k] = l;
    }
}

// ---------------- prep: split + transpose Wb, Wc -> g_WBCh/l [32][DM] ----------------
__global__ __launch_bounds__(256)
void split_wbc_kernel(const float* __restrict__ Wb, const float* __restrict__ Wc) {
    int i = blockIdx.x * 256 + threadIdx.x;   // 0..32767
    float v; int row, k;
    if (i < ST * DM) {
        row = i & 15; k = i >> 4; v = Wb[i];
    } else {
        int j = i - ST * DM;
        row = 16 + (j & 15); k = j >> 4; v = Wc[j];
    }
    __nv_bfloat16 h = __float2bfloat16_rn(v);
    __nv_bfloat16 l = __float2bfloat16_rn(v - __bfloat162float(h));
    g_WBCh[(size_t)row * DM + k] = h;
    g_WBCl[(size_t)row * DM + k] = l;
}

// ---------------- transpose x [MROWS,DM] -> g_xT [DM,MROWS] ----------------
__global__ __launch_bounds__(256)
void transpose_in_kernel(const float* __restrict__ in) {
    __shared__ float tile[32][33];
    const int c0 = blockIdx.x * 32, r0 = blockIdx.y * 32;
    const int tx = threadIdx.x, ty = threadIdx.y;
#pragma unroll
    for (int j = 0; j < 32; j += 8)
        tile[ty + j][tx] = in[(size_t)(r0 + ty + j) * DM + c0 + tx];
    __syncthreads();
#pragma unroll
    for (int j = 0; j < 32; j += 8)
        g_xT[(size_t)(c0 + ty + j) * MROWS + r0 + tx] = tile[tx][ty + j];
}

// ================== bf16-split mma GEMM, cp.async double-buffered ==================
// Block 128x64, BK=32. 8 warps = 4M x 2N, warp tile 32x32. 3 products.
__global__ __launch_bounds__(256, 2)
void gemm_main_kernel(const float* __restrict__ bias) {
    __shared__ __nv_bfloat16 sAh[2][128 * 32], sAl[2][128 * 32];   // 16 KB each pair
    __shared__ __nv_bfloat16 sBh[2][64 * 32],  sBl[2][64 * 32];    //  8 KB each pair

    const int tid = threadIdx.x, lane = tid & 31, wid = tid >> 5;
    const int wm = wid & 3, wn = wid >> 2;
    const int bm = blockIdx.y * 128, bn = blockIdx.x * 64;

    const int r1 = tid >> 2, c1 = tid & 3;        // loader: rows 0..63, 4 chunks
    uint32_t aAh[2] = {smem_u32(sAh[0]), smem_u32(sAh[1])};
    uint32_t aAl[2] = {smem_u32(sAl[0]), smem_u32(sAl[1])};
    uint32_t aBh[2] = {smem_u32(sBh[0]), smem_u32(sBh[1])};
    uint32_t aBl[2] = {smem_u32(sBl[0]), smem_u32(sBl[1])};

    const int sub = lane >> 3;
    const int la_r  = wm * 32 + (sub & 1) * 8 + (lane & 7);
    const int la_c8 = sub >> 1;
    const int lb_n  = wn * 32 + (sub >> 1) * 8 + (lane & 7);
    const int lb_c8 = sub & 1;

    float acc[2][4][4];
#pragma unroll
    for (int i = 0; i < 2; ++i)
#pragma unroll
        for (int j = 0; j < 4; ++j)
#pragma unroll
            for (int r = 0; r < 4; ++r) acc[i][j][r] = 0.f;

    const __nv_bfloat16* Ah0 = g_Xh + (size_t)(bm + r1) * DM + c1 * 8;
    const __nv_bfloat16* Ah1 = g_Xh + (size_t)(bm + 64 + r1) * DM + c1 * 8;
    const __nv_bfloat16* Al0 = g_Xl + (size_t)(bm + r1) * DM + c1 * 8;
    const __nv_bfloat16* Al1 = g_Xl + (size_t)(bm + 64 + r1) * DM + c1 * 8;
    const __nv_bfloat16* Bh0 = g_Wh + (size_t)(bn + r1) * DM + c1 * 8;
    const __nv_bfloat16* Bl0 = g_Wl + (size_t)(bn + r1) * DM + c1 * 8;

    const uint32_t oA0 = SWC(r1, c1), oA1 = SWC(64 + r1, c1), oB = SWC(r1, c1);

    // prologue: stage 0 into buffer 0
    cp16(aAh[0] + oA0, Ah0);
    cp16(aAh[0] + oA1, Ah1);
    cp16(aAl[0] + oA0, Al0);
    cp16(aAl[0] + oA1, Al1);
    cp16(aBh[0] + oB, Bh0);
    cp16(aBl[0] + oB, Bl0);
    CP_COMMIT();

    for (int s = 0; s < 32; ++s) {
        const int cur = s & 1, nxt = cur ^ 1;
        if (s + 1 < 32) {
            const int k0 = (s + 1) * 32;
            cp16(aAh[nxt] + oA0, Ah0 + k0);
            cp16(aAh[nxt] + oA1, Ah1 + k0);
            cp16(aAl[nxt] + oA0, Al0 + k0);
            cp16(aAl[nxt] + oA1, Al1 + k0);
            cp16(aBh[nxt] + oB, Bh0 + k0);
            cp16(aBl[nxt] + oB, Bl0 + k0);
        }
        CP_COMMIT();
        CP_WAIT1();
        __syncthreads();

#pragma unroll
        for (int kh = 0; kh < 2; ++kh) {
            uint32_t Afh[2][4], Afl[2][4], Bfh[2][4], Bfl[2][4];
#pragma unroll
            for (int i = 0; i < 2; ++i) {
                ldsm_x4(Afh[i], aAh[cur] + SWC(la_r + i * 16, kh * 2 + la_c8));
                ldsm_x4(Afl[i], aAl[cur] + SWC(la_r + i * 16, kh * 2 + la_c8));
            }
#pragma unroll
            for (int p = 0; p < 2; ++p) {
                ldsm_x4(Bfh[p], aBh[cur] + SWC(lb_n + p * 16, kh * 2 + lb_c8));
                ldsm_x4(Bfl[p], aBl[cur] + SWC(lb_n + p * 16, kh * 2 + lb_c8));
            }
#pragma unroll
            for (int i = 0; i < 2; ++i)
#pragma unroll
                for (int j = 0; j < 4; ++j) {
                    const uint32_t* bh = &Bfh[j >> 1][(j & 1) * 2];
                    const uint32_t* bl = &Bfl[j >> 1][(j & 1) * 2];
                    mma_bf16(acc[i][j], Afh[i], bh);
                    mma_bf16(acc[i][j], Afl[i], bh);
                    mma_bf16(acc[i][j], Afh[i], bl);
                }
        }
        __syncthreads();
    }

    // epilogue: +bias, softplus, transposed store
    const int g = lane >> 2, t = lane & 3;
#pragma unroll
    for (int i = 0; i < 2; ++i) {
        const int row = bm + wm * 32 + i * 16 + g;
#pragma unroll
        for (int j = 0; j < 4; ++j) {
            const int col = bn + wn * 32 + j * 8 + t * 2;
            const float b0 = bias[col], b1 = bias[col + 1];
            g_deltaT[(size_t)col * MROWS + row]           = softplus_f(acc[i][j][0] + b0);
            g_deltaT[(size_t)(col + 1) * MROWS + row]     = softplus_f(acc[i][j][1] + b1);
            g_deltaT[(size_t)col * MROWS + row + 8]       = softplus_f(acc[i][j][2] + b0);
            g_deltaT[(size_t)(col + 1) * MROWS + row + 8] = softplus_f(acc[i][j][3] + b1);
        }
    }
}

// ================== bf16-split mma GEMM for B/C (unchanged from R7, correct) ==================
__global__ __launch_bounds__(256, 2)
void gemm_bc_kernel(const float* __restrict__ bb, const float* __restrict__ bc) {
    __shared__ __nv_bfloat16 sAh[128 * 32], sAl[128 * 32];
    __shared__ __nv_bfloat16 sBh[32 * 32],  sBl[32 * 32];

    const int tid = threadIdx.x, lane = tid & 31, wid = tid >> 5;
    const int wm = wid & 3, wn = wid >> 2;
    const int bm = blockIdx.x * 128;

    const int r1 = tid >> 2, c1 = tid & 3;
    const int tb = tid & 127;
    const int rB = tb >> 2, cB = tb & 3;
    const uint32_t aAh = smem_u32(sAh), aAl = smem_u32(sAl);
    const uint32_t aBh = smem_u32(sBh), aBl = smem_u32(sBl);

    const int sub = lane >> 3;
    const int la_r  = wm * 32 + (sub & 1) * 8 + (lane & 7);
    const int la_c8 = sub >> 1;
    const int lb_n  = wn * 16 + (sub >> 1) * 8 + (lane & 7);
    const int lb_c8 = sub & 1;

    float acc[2][2][4];
#pragma unroll
    for (int i = 0; i < 2; ++i)
#pragma unroll
        for (int j = 0; j < 2; ++j)
#pragma unroll
            for (int r = 0; r < 4; ++r) acc[i][j][r] = 0.f;

    const __nv_bfloat16* Ah0 = g_Xh + (size_t)(bm + r1) * DM;
    const __nv_bfloat16* Ah1 = g_Xh + (size_t)(bm + 64 + r1) * DM;
    const __nv_bfloat16* Al0 = g_Xl + (size_t)(bm + r1) * DM;
    const __nv_bfloat16* Al1 = g_Xl + (size_t)(bm + 64 + r1) * DM;
    const __nv_bfloat16* Bsrc = ((tid < 128) ? g_WBCh : g_WBCl) + (size_t)rB * DM;
    char* sBdst = (char*)((tid < 128) ? sBh : sBl);

    uint4 pAh0 = *(const uint4*)(Ah0 + c1 * 8);
    uint4 pAh1 = *(const uint4*)(Ah1 + c1 * 8);
    uint4 pAl0 = *(const uint4*)(Al0 + c1 * 8);
    uint4 pAl1 = *(const uint4*)(Al1 + c1 * 8);
    uint4 pB   = *(const uint4*)(Bsrc + cB * 8);

    for (int s = 0; s < 32; ++s) {
        *(uint4*)((char*)sAh + SWC(r1, c1))      = pAh0;
        *(uint4*)((char*)sAh + SWC(64 + r1, c1)) = pAh1;
        *(uint4*)((char*)sAl + SWC(r1, c1))      = pAl0;
        *(uint4*)((char*)sAl + SWC(64 + r1, c1)) = pAl1;
        *(uint4*)(sBdst + SWC(rB, cB))           = pB;
        __syncthreads();

        if (s + 1 < 32) {
            const int k0 = (s + 1) * 32;
            pAh0 = *(const uint4*)(Ah0 + k0 + c1 * 8);
            pAh1 = *(const uint4*)(Ah1 + k0 + c1 * 8);
            pAl0 = *(const uint4*)(Al0 + k0 + c1 * 8);
            pAl1 = *(const uint4*)(Al1 + k0 + c1 * 8);
            pB   = *(const uint4*)(Bsrc + k0 + cB * 8);
        }

#pragma unroll
        for (int kh = 0; kh < 2; ++kh) {
            uint32_t Afh[2][4], Afl[2][4], Bfh[4], Bfl[4];
#pragma unroll
            for (int i = 0; i < 2; ++i) {
                ldsm_x4(Afh[i], aAh + SWC(la_r + i * 16, kh * 2 + la_c8));
                ldsm_x4(Afl[i], aAl + SWC(la_r + i * 16, kh * 2 + la_c8));
            }
            ldsm_x4(Bfh, aBh + SWC(lb_n, kh * 2 + lb_c8));
            ldsm_x4(Bfl, aBl + SWC(lb_n, kh * 2 + lb_c8));
#pragma unroll
            for (int i = 0; i < 2; ++i)
#pragma unroll
                for (int j = 0; j < 2; ++j) {
                    mma_bf16(acc[i][j], Afh[i], &Bfh[j * 2]);
                    mma_bf16(acc[i][j], Afl[i], &Bfh[j * 2]);
                    mma_bf16(acc[i][j], Afh[i], &Bfl[j * 2]);
                }
        }
        __syncthreads();
    }

    const int g = lane >> 2, t = lane & 3;
    float* out = (float*)g_BC;
#pragma unroll
    for (int i = 0; i < 2; ++i) {
        const int row = bm + wm * 32 + i * 16 + g;
#pragma unroll
        for (int j = 0; j < 2; ++j) {
            const int n0 = j * 8 + t * 2;
            const float bv0 = wn ? bc[n0] : bb[n0];
            const float bv1 = wn ? bc[n0 + 1] : bb[n0 + 1];
            out[((size_t)row * ST + n0) * 2 + wn]           = acc[i][j][0] + bv0;
            out[((size_t)row * ST + n0 + 1) * 2 + wn]       = acc[i][j][1] + bv1;
            out[((size_t)(row + 8) * ST + n0) * 2 + wn]     = acc[i][j][2] + bv0;
            out[((size_t)(row + 8) * ST + n0 + 1) * 2 + wn] = acc[i][j][3] + bv1;
        }
    }
}

// ---------------- scan v4: phase-separated unroll-8, interleaved shfl trees ----------------
__global__ __launch_bounds__(256)
void scan4_kernel(const float* __restrict__ A_log, const float* __restrict__ D_skip,
                  float* __restrict__ y) {
    const int gw   = blockIdx.x * 8 + (threadIdx.x >> 5);   // 0..2047
    const int lane = threadIdx.x & 31;
    const int half = lane >> 4;
    const int n    = lane & 15;

    const int b     = gw >> 9;
    const int dpair = gw & 511;
    const int d     = dpair * 2 + half;

    const float A   = -__expf(A_log[d * ST + n]);
    const float dsk = D_skip[d];

    const float*  xp  = g_xT     + (size_t)d * MROWS + b * SEQ;
    const float*  dp  = g_deltaT + (size_t)d * MROWS + b * SEQ;
    const float2* bcp = g_BC     + (size_t)b * SEQ * ST + n;
    float*        yp  = y        + ((size_t)b * SEQ) * DM + d;

    float h = 0.f;
    for (int t0 = 0; t0 < SEQ; t0 += 8) {
        float4 xa = *(const float4*)(xp + t0);
        float4 xb = *(const float4*)(xp + t0 + 4);
        float4 da = *(const float4*)(dp + t0);
        float4 db = *(const float4*)(dp + t0 + 4);
        float2 bcv[8];
#pragma unroll
        for (int j = 0; j < 8; ++j) bcv[j] = bcp[(size_t)(t0 + j) * ST];

        const float xs[8] = {xa.x, xa.y, xa.z, xa.w, xb.x, xb.y, xb.z, xb.w};
        const float ds[8] = {da.x, da.y, da.z, da.w, db.x, db.y, db.z, db.w};

        float p[8];
#pragma unroll
        for (int j = 0; j < 8; ++j) {
            const float bar = __expf(ds[j] * A);
            h = fmaf(bar, h, ds[j] * xs[j] * bcv[j].x);
            p[j] = h * bcv[j].y;
        }
        // 8 independent reduction trees, level-interleaved
#pragma unroll
        for (int j = 0; j < 8; ++j) p[j] += __shfl_xor_sync(0xffffffffu, p[j], 8);
#pragma unroll
        for (int j = 0; j < 8; ++j) p[j] += __shfl_xor_sync(0xffffffffu, p[j], 4);
#pragma unroll
        for (int j = 0; j < 8; ++j) p[j] += __shfl_xor_sync(0xffffffffu, p[j], 2);
#pragma unroll
        for (int j = 0; j < 8; ++j) p[j] += __shfl_xor_sync(0xffffffffu, p[j], 1);

        if (n == 0) {
#pragma unroll
            for (int j = 0; j < 8; ++j)
                yp[(size_t)(t0 + j) * DM] = fmaf(xs[j], dsk, p[j]);
        }
    }
}

// ---------------- launch (gemm_main in ncu capture slot #4) ----------------
extern "C" void kernel_launch(void* const* d_in, const int* in_sizes, int n_in,
                              void* d_out, int out_size) {
    (void)in_sizes; (void)n_in; (void)out_size;
    const float* x     = (const float*)d_in[0];
    const float* A_log = (const float*)d_in[1];
    const float* Dsk   = (const float*)d_in[2];
    const float* Wd    = (const float*)d_in[3];
    const float* bd    = (const float*)d_in[4];
    const float* Wb    = (const float*)d_in[5];
    const float* bb    = (const float*)d_in[6];
    const float* Wc    = (const float*)d_in[7];
    const float* bc    = (const float*)d_in[8];
    float* y = (float*)d_out;

    split_x_kernel<<<MROWS * DM / 4 / 256, 256>>>(x);                       // 1
    split_wt_kernel<<<dim3(32, 32), dim3(32, 8)>>>(Wd);                     // 2
    split_wbc_kernel<<<2 * ST * DM / 256, 256>>>(Wb, Wc);                   // 3
    gemm_main_kernel<<<dim3(DM / 64, MROWS / 128), 256>>>(bd);              // 4 <- profiled
    transpose_in_kernel<<<dim3(DM / 32, MROWS / 32), dim3(32, 8)>>>(x);     // 5
    gemm_bc_kernel<<<MROWS / 128, 256>>>(bb, bc);                           // 6
    scan4_kernel<<<256, 256>>>(A_log, Dsk, y);                              // 7
}